// round 8
// baseline (speedup 1.0000x reference)
#include <cuda_runtime.h>

#define DEVINLINE __device__ __forceinline__

constexpr int BATCH = 100;
constexpr int BPAD  = 128;   // padded batch stride for feature-major layouts

// --- fc coefficient offsets (gates, float4 units) ---
constexpr int OFF_FC1 = 0;        // 20480
constexpr int OFF_FC2 = 20480;    // 10240
constexpr int OFF_FC3 = 30720;    // 5120
constexpr int N_FCC   = 35840;

// conv descriptor slots (float4 units): 10 slots per filter
constexpr int DESC_C1 = 0;            // 16 filters
constexpr int DESC_C2 = 16 * 10;      // 48 filters
constexpr int DESC_C3 = 64 * 10;      // 144 filters
constexpr int N_DESC  = 208 * 10;

// --- scratch (device globals; zero-initialized; halos never written) ---
__device__ float4 g_coef[N_FCC];
__device__ float4 g_desc[N_DESC];
__device__ float  g_p1[BATCH * 16 * 14 * 14];   // conv1 pooled, halo=1, [B][16][14][14]
__device__ float  g_p2[BATCH * 48 * 8 * 8];     // conv2 pooled, halo=1, [B][48][8][8]
__device__ float  g_p3T[1296 * BPAD];           // conv3 pooled, feature-major [1296][BPAD]
__device__ float  g_f1T[20480 * BPAD];          // fc1 out, feature-major
__device__ float  g_f2T[10240 * BPAD];          // fc2 out, feature-major

// softmax(w[16]) -> fused gate coefficients (C, A, B, D):  op = C + A*a + B*b + D*ab
DEVINLINE float4 softcoef(const float* __restrict__ w) {
    float v[16];
    float mx = -1e30f;
    #pragma unroll
    for (int i = 0; i < 16; i++) { v[i] = w[i]; mx = fmaxf(mx, v[i]); }
    float sum = 0.f;
    #pragma unroll
    for (int i = 0; i < 16; i++) { v[i] = __expf(v[i] - mx); sum += v[i]; }
    float inv = 1.0f / sum;
    #pragma unroll
    for (int i = 0; i < 16; i++) v[i] *= inv;
    float C = v[8] + v[9] + v[10] + v[11] + v[12] + v[13] + v[14] + v[15];
    float A = v[2] + v[3] + v[6] + v[7] - v[8] - v[9] - v[12] - v[13];
    float B = v[4] + v[5] + v[6] + v[7] - v[8] - v[9] - v[10] - v[11];
    float D = v[1] - v[2] - v[4] - 2.f * v[6] - v[7]
            + v[8] + 2.f * v[9] + v[11] + v[13] - v[14];
    return make_float4(C, A, B, D);
}

DEVINLINE float gate(float a, float b, float4 k) {
    return fmaf(a, fmaf(k.w, b, k.y), fmaf(k.z, b, k.x));
}

DEVINLINE float pick4(const float h[4], int i) {
    float r = h[0];
    r = (i == 1) ? h[1] : r;
    r = (i == 2) ? h[2] : r;
    r = (i == 3) ? h[3] : r;
    return r;
}

// ============================================================================
// Prep kernel: fc coefficients and conv filter descriptors (batch-tile offsets).
// ============================================================================
struct PrepArgs {
    const float* fc1w; const float* fc2w; const float* fc3w;
    const int*   ci0[3]; const int* ci1[3]; const int* ci2[3];
    const float* cw0[3]; const float* cw1[3]; const float* cw2[3];
};

__constant__ int c_F[3]    = {16, 48, 144};
__constant__ int c_KS[3]   = {5, 3, 3};
__constant__ int c_CSTR[3] = {784, 196, 64};  // channel stride within one batch tile
__constant__ int c_WPAD[3] = {28, 14, 8};     // (padded) tile row width
__constant__ int c_DOFF[3] = {DESC_C1, DESC_C2, DESC_C3};

__global__ void prep_kernel(PrepArgs args) {
    int tid = blockIdx.x * blockDim.x + threadIdx.x;
    if (tid < N_FCC) {
        const float* w;
        int g;
        if (tid < OFF_FC2)      { w = args.fc1w; g = tid; }
        else if (tid < OFF_FC3) { w = args.fc2w; g = tid - OFF_FC2; }
        else                    { w = args.fc3w; g = tid - OFF_FC3; }
        g_coef[tid] = softcoef(w + (size_t)g * 16);
        return;
    }
    int j = tid - N_FCC;
    if (j >= 208) return;
    int layer, f;
    if (j < 16)      { layer = 0; f = j; }
    else if (j < 64) { layer = 1; f = j - 16; }
    else             { layer = 2; f = j - 64; }

    int F = c_F[layer], KS = c_KS[layer], CSTR = c_CSTR[layer], WP = c_WPAD[layer];
    const int* i0 = args.ci0[layer];
    const int* i1 = args.ci1[layer];
    const int* i2 = args.ci2[layer];
    float4* dst = g_desc + c_DOFF[layer] + f * 10;

    int offA[4], offB[4];
    #pragma unroll
    for (int g = 0; g < 4; g++) {
        int ta = i0[f * 4 + g], tb = i0[F * 4 + f * 4 + g];
        int ca = ta / (KS * KS), ra = ta - ca * KS * KS;
        int cb = tb / (KS * KS), rb = tb - cb * KS * KS;
        offA[g] = ca * CSTR + (ra / KS) * WP + (ra % KS);
        offB[g] = cb * CSTR + (rb / KS) * WP + (rb % KS);
        dst[2 + g] = softcoef(args.cw0[layer] + (size_t)(f * 4 + g) * 16);
    }
    dst[0] = make_float4(__int_as_float(offA[0]), __int_as_float(offA[1]),
                         __int_as_float(offA[2]), __int_as_float(offA[3]));
    dst[1] = make_float4(__int_as_float(offB[0]), __int_as_float(offB[1]),
                         __int_as_float(offB[2]), __int_as_float(offB[3]));
    int pk = 0;
    #pragma unroll
    for (int g = 0; g < 2; g++) {
        pk |= (i1[f * 2 + g] & 3) << (4 * g);
        pk |= (i1[F * 2 + f * 2 + g] & 3) << (4 * g + 2);
        dst[6 + g] = softcoef(args.cw1[layer] + (size_t)(f * 2 + g) * 16);
    }
    pk |= (i2[f] & 1) << 8;
    pk |= (i2[F + f] & 1) << 9;
    dst[8] = softcoef(args.cw2[layer] + (size_t)f * 16);
    dst[9] = make_float4(__int_as_float(pk), 0.f, 0.f, 0.f);
}

// ============================================================================
// Conv(logic-tree) + 2x2 max-pool, pool window split across 4 lanes.
// One thread = one pre-pool position; shfl_xor max; lane dd==0 stores.
// 4x thread count vs one-thread-per-pooled-output (occupancy fix).
// ============================================================================
template <int F, int POH, int POW, int BSTR, int WPAD, bool BIN,
          int OBSTR, int OFSTR, int OW, int OHALO, int DOFF, bool TRANS>
__global__ __launch_bounds__(256)
void conv_kernel(const float* __restrict__ in, float* __restrict__ out) {
    constexpr int NP = POH * POW;
    int tid = blockIdx.x * blockDim.x + threadIdx.x;   // exact grid, no guard
    int dd = tid & 3;
    int t  = tid >> 2;
    int pj = t % POW; t /= POW;
    int pi = t % POH; t /= POH;
    int f  = t % F;
    int b  = t / F;

    const float4* D = g_desc + DOFF + f * 10;
    float4 s0 = __ldg(D + 0), s1 = __ldg(D + 1);
    int oa[4] = {__float_as_int(s0.x), __float_as_int(s0.y),
                 __float_as_int(s0.z), __float_as_int(s0.w)};
    int ob[4] = {__float_as_int(s1.x), __float_as_int(s1.y),
                 __float_as_int(s1.z), __float_as_int(s1.w)};
    float4 k0[4] = {__ldg(D + 2), __ldg(D + 3), __ldg(D + 4), __ldg(D + 5)};
    float4 k1[2] = {__ldg(D + 6), __ldg(D + 7)};
    float4 k2 = __ldg(D + 8);
    int pk = __float_as_int(__ldg(D + 9).x);
    int a10 = pk & 3, b10 = (pk >> 2) & 3, a11 = (pk >> 4) & 3, b11 = (pk >> 6) & 3;
    int a2 = (pk >> 8) & 1, b2 = (pk >> 9) & 1;

    const float* inb = in + (size_t)b * BSTR;
    int base = (2 * pi + (dd >> 1)) * WPAD + 2 * pj + (dd & 1);

    float h0[4];
    #pragma unroll
    for (int g = 0; g < 4; g++) {
        float av = __ldg(inb + base + oa[g]);
        float bv = __ldg(inb + base + ob[g]);
        if (BIN) { av = (av > 0.5f) ? 1.f : 0.f; bv = (bv > 0.5f) ? 1.f : 0.f; }
        h0[g] = gate(av, bv, k0[g]);
    }
    float h1[2];
    h1[0] = gate(pick4(h0, a10), pick4(h0, b10), k1[0]);
    h1[1] = gate(pick4(h0, a11), pick4(h0, b11), k1[1]);
    float v = gate(a2 ? h1[1] : h1[0], b2 ? h1[1] : h1[0], k2);

    // 2x2 max across the 4-lane pool group
    v = fmaxf(v, __shfl_xor_sync(0xffffffffu, v, 1));
    v = fmaxf(v, __shfl_xor_sync(0xffffffffu, v, 2));
    if (dd == 0) {
        if (TRANS) {
            int o = f * NP + pi * POW + pj;
            out[o * BPAD + b] = v;
        } else {
            out[(size_t)b * OBSTR + f * OFSTR + (pi + OHALO) * OW + (pj + OHALO)] = v;
        }
    }
}

// ============================================================================
// FC layers, feature-major: warp = (output gate, batch quarter); lane = batch.
// Gathers are coalesced 128B line reads; idx/coef loads warp-uniform.
// ============================================================================
template <int DOUT, int COFF>
__global__ __launch_bounds__(256)
void fc_kernel(const float* __restrict__ inT, const int* __restrict__ idx,
               float* __restrict__ outT) {
    int w = blockIdx.x * 8 + (threadIdx.x >> 5);   // global warp id
    int lane = threadIdx.x & 31;
    int o  = w >> 2;
    int b  = (w & 3) * 32 + lane;
    int ia = __ldg(idx + o);
    int ib = __ldg(idx + DOUT + o);
    float4 k = g_coef[COFF + o];
    float v = gate(inT[ia * BPAD + b], inT[ib * BPAD + b], k);
    outT[o * BPAD + b] = v;   // pad lanes write garbage into pad columns (never read as valid)
}

// fc3 + GroupSum(k=10, tau=30). grid = (10 groups, 4 batch-quarters), block 512.
__global__ __launch_bounds__(512)
void fc3_sum_kernel(const int* __restrict__ idx, float* __restrict__ out) {
    int grp = blockIdx.x, bq = blockIdx.y;
    int tid = threadIdx.x;
    int lane = tid & 31;
    int w = tid >> 5;                      // 0..15
    int b = bq * 32 + lane;

    float v = 0.f;
    #pragma unroll 4
    for (int kk = 0; kk < 32; kk++) {
        int o = grp * 512 + w * 32 + kk;
        int ia = __ldg(idx + o);
        int ib = __ldg(idx + 5120 + o);
        float4 c = g_coef[OFF_FC3 + o];
        v += gate(g_f2T[ia * BPAD + b], g_f2T[ib * BPAD + b], c);
    }
    __shared__ float sdata[16][33];
    sdata[w][lane] = v;
    __syncthreads();
    if (tid < 32) {
        float s = 0.f;
        #pragma unroll
        for (int ww = 0; ww < 16; ww++) s += sdata[ww][lane];
        if (b < BATCH) out[b * 10 + grp] = s / 30.0f;
    }
}

// ============================================================================
// Launch
// ============================================================================
extern "C" void kernel_launch(void* const* d_in, const int* in_sizes, int n_in,
                              void* d_out, int out_size) {
    const float* x    = (const float*)d_in[0];
    const int*   c1i0 = (const int*)d_in[1];   const float* c1w0 = (const float*)d_in[2];
    const int*   c1i1 = (const int*)d_in[3];   const float* c1w1 = (const float*)d_in[4];
    const int*   c1i2 = (const int*)d_in[5];   const float* c1w2 = (const float*)d_in[6];
    const int*   c2i0 = (const int*)d_in[7];   const float* c2w0 = (const float*)d_in[8];
    const int*   c2i1 = (const int*)d_in[9];   const float* c2w1 = (const float*)d_in[10];
    const int*   c2i2 = (const int*)d_in[11];  const float* c2w2 = (const float*)d_in[12];
    const int*   c3i0 = (const int*)d_in[13];  const float* c3w0 = (const float*)d_in[14];
    const int*   c3i1 = (const int*)d_in[15];  const float* c3w1 = (const float*)d_in[16];
    const int*   c3i2 = (const int*)d_in[17];  const float* c3w2 = (const float*)d_in[18];
    const int*   fc1i = (const int*)d_in[19];  const float* fc1w = (const float*)d_in[20];
    const int*   fc2i = (const int*)d_in[21];  const float* fc2w = (const float*)d_in[22];
    const int*   fc3i = (const int*)d_in[23];  const float* fc3w = (const float*)d_in[24];
    float* out = (float*)d_out;

    float *p1, *p2, *p3T, *f1T, *f2T;
    cudaGetSymbolAddress((void**)&p1,  g_p1);
    cudaGetSymbolAddress((void**)&p2,  g_p2);
    cudaGetSymbolAddress((void**)&p3T, g_p3T);
    cudaGetSymbolAddress((void**)&f1T, g_f1T);
    cudaGetSymbolAddress((void**)&f2T, g_f2T);

    // 1) prep: fc coefs + conv filter descriptors
    PrepArgs pa;
    pa.fc1w = fc1w; pa.fc2w = fc2w; pa.fc3w = fc3w;
    pa.ci0[0] = c1i0; pa.ci1[0] = c1i1; pa.ci2[0] = c1i2;
    pa.cw0[0] = c1w0; pa.cw1[0] = c1w1; pa.cw2[0] = c1w2;
    pa.ci0[1] = c2i0; pa.ci1[1] = c2i1; pa.ci2[1] = c2i2;
    pa.cw0[1] = c2w0; pa.cw1[1] = c2w1; pa.cw2[1] = c2w2;
    pa.ci0[2] = c3i0; pa.ci1[2] = c3i1; pa.ci2[2] = c3i2;
    pa.cw0[2] = c3w0; pa.cw1[2] = c3w1; pa.cw2[2] = c3w2;
    prep_kernel<<<(N_FCC + 208 + 255) / 256, 256>>>(pa);

    // 2) conv1 + pool: x[100,784] -> p1 [B][16][14][14] halo=1   (921600 threads)
    conv_kernel<16, 12, 12, 784, 28, true, 3136, 196, 14, 1, DESC_C1, false>
        <<<BATCH * 16 * 144 * 4 / 256, 256>>>(x, p1);
    // 3) conv2 + pool: p1 -> p2 [B][48][8][8] halo=1             (691200 threads)
    conv_kernel<48, 6, 6, 3136, 14, false, 3072, 64, 8, 1, DESC_C2, false>
        <<<BATCH * 48 * 36 * 4 / 256, 256>>>(p1, p2);
    // 4) conv3 + pool: p2 -> p3T [1296][BPAD] feature-major      (518400 threads)
    conv_kernel<144, 3, 3, 3072, 8, false, 0, 0, 0, 0, DESC_C3, true>
        <<<BATCH * 144 * 9 * 4 / 256, 256>>>(p2, p3T);
    // 5) fc1: 1296 -> 20480, warp=(o, bq), lane=batch            (81920 warps)
    fc_kernel<20480, OFF_FC1><<<20480 * 4 / 8, 256>>>(p3T, fc1i, f1T);
    // 6) fc2: 20480 -> 10240                                     (40960 warps)
    fc_kernel<10240, OFF_FC2><<<10240 * 4 / 8, 256>>>(f1T, fc2i, f2T);
    // 7) fc3 + group sum -> [100, 10]
    {
        dim3 grid(10, 4);
        fc3_sum_kernel<<<grid, 512>>>(fc3i, out);
    }
    (void)in_sizes; (void)n_in; (void)out_size;
}

// round 10
// speedup vs baseline: 1.0810x; 1.0810x over previous
#include <cuda_runtime.h>

#define DEVINLINE __device__ __forceinline__

constexpr int BATCH = 100;
constexpr int BPAD  = 128;   // padded batch stride; lane = batch

// --- fc coefficient offsets (gates, float4 units) ---
constexpr int OFF_FC1 = 0;        // 20480
constexpr int OFF_FC2 = 20480;    // 10240
constexpr int OFF_FC3 = 30720;    // 5120
constexpr int N_FCC   = 35840;

// conv descriptor slots (float4 units): 10 slots per filter
constexpr int DESC_C1 = 0;            // 16 filters
constexpr int DESC_C2 = 16 * 10;      // 48 filters
constexpr int DESC_C3 = 64 * 10;      // 144 filters
constexpr int N_DESC  = 208 * 10;

// --- scratch (device globals; zero-initialized; halo positions never written) ---
__device__ float4 g_coef[N_FCC];
__device__ float4 g_desc[N_DESC];
__device__ float  g_xT [784 * BPAD];            // binarized input, [pos][BPAD]
__device__ float  g_p1T[16 * 196 * BPAD];       // conv1 pooled, halo=1: [f*196 + (pi+1)*14 + (pj+1)][BPAD]
__device__ float  g_p2T[48 * 64 * BPAD];        // conv2 pooled, halo=1: [f*64 + (pi+1)*8 + (pj+1)][BPAD]
__device__ float  g_p3T[1296 * BPAD];           // conv3 pooled: [f*9 + pi*3 + pj][BPAD] (ref flatten order)
__device__ float  g_f1T[20480 * BPAD];
__device__ float  g_f2T[10240 * BPAD];

// softmax(w[16]) -> fused gate coefficients (C, A, B, D):  op = C + A*a + B*b + D*ab
DEVINLINE float4 softcoef(const float* __restrict__ w) {
    float v[16];
    float mx = -1e30f;
    #pragma unroll
    for (int i = 0; i < 16; i++) { v[i] = w[i]; mx = fmaxf(mx, v[i]); }
    float sum = 0.f;
    #pragma unroll
    for (int i = 0; i < 16; i++) { v[i] = __expf(v[i] - mx); sum += v[i]; }
    float inv = 1.0f / sum;
    #pragma unroll
    for (int i = 0; i < 16; i++) v[i] *= inv;
    float C = v[8] + v[9] + v[10] + v[11] + v[12] + v[13] + v[14] + v[15];
    float A = v[2] + v[3] + v[6] + v[7] - v[8] - v[9] - v[12] - v[13];
    float B = v[4] + v[5] + v[6] + v[7] - v[8] - v[9] - v[10] - v[11];
    float D = v[1] - v[2] - v[4] - 2.f * v[6] - v[7]
            + v[8] + 2.f * v[9] + v[11] + v[13] - v[14];
    return make_float4(C, A, B, D);
}

DEVINLINE float gate(float a, float b, float4 k) {
    return fmaf(a, fmaf(k.w, b, k.y), fmaf(k.z, b, k.x));
}

DEVINLINE float pick4(const float h[4], int i) {
    float r = h[0];
    r = (i == 1) ? h[1] : r;
    r = (i == 2) ? h[2] : r;
    r = (i == 3) ? h[3] : r;
    return r;
}

// ============================================================================
// Prep kernel: fc coefficients + conv filter descriptors.
// Conv gather offsets are in POSITION space, pre-scaled by BPAD.
// ============================================================================
struct PrepArgs {
    const float* fc1w; const float* fc2w; const float* fc3w;
    const int*   ci0[3]; const int* ci1[3]; const int* ci2[3];
    const float* cw0[3]; const float* cw1[3]; const float* cw2[3];
};

__constant__ int c_F[3]    = {16, 48, 144};
__constant__ int c_KS[3]   = {5, 3, 3};
__constant__ int c_CSTR[3] = {784, 196, 64};  // channel stride (positions) in input
__constant__ int c_WPAD[3] = {28, 14, 8};     // (padded) input row width (positions)
__constant__ int c_DOFF[3] = {DESC_C1, DESC_C2, DESC_C3};

__global__ void prep_kernel(PrepArgs args) {
    int tid = blockIdx.x * blockDim.x + threadIdx.x;
    if (tid < N_FCC) {
        const float* w;
        int g;
        if (tid < OFF_FC2)      { w = args.fc1w; g = tid; }
        else if (tid < OFF_FC3) { w = args.fc2w; g = tid - OFF_FC2; }
        else                    { w = args.fc3w; g = tid - OFF_FC3; }
        g_coef[tid] = softcoef(w + (size_t)g * 16);
        return;
    }
    int j = tid - N_FCC;
    if (j >= 208) return;
    int layer, f;
    if (j < 16)      { layer = 0; f = j; }
    else if (j < 64) { layer = 1; f = j - 16; }
    else             { layer = 2; f = j - 64; }

    int F = c_F[layer], KS = c_KS[layer], CSTR = c_CSTR[layer], WP = c_WPAD[layer];
    const int* i0 = args.ci0[layer];
    const int* i1 = args.ci1[layer];
    const int* i2 = args.ci2[layer];
    float4* dst = g_desc + c_DOFF[layer] + f * 10;

    int offA[4], offB[4];
    #pragma unroll
    for (int g = 0; g < 4; g++) {
        int ta = i0[f * 4 + g], tb = i0[F * 4 + f * 4 + g];
        int ca = ta / (KS * KS), ra = ta - ca * KS * KS;
        int cb = tb / (KS * KS), rb = tb - cb * KS * KS;
        offA[g] = (ca * CSTR + (ra / KS) * WP + (ra % KS)) * BPAD;
        offB[g] = (cb * CSTR + (rb / KS) * WP + (rb % KS)) * BPAD;
        dst[2 + g] = softcoef(args.cw0[layer] + (size_t)(f * 4 + g) * 16);
    }
    dst[0] = make_float4(__int_as_float(offA[0]), __int_as_float(offA[1]),
                         __int_as_float(offA[2]), __int_as_float(offA[3]));
    dst[1] = make_float4(__int_as_float(offB[0]), __int_as_float(offB[1]),
                         __int_as_float(offB[2]), __int_as_float(offB[3]));
    int pk = 0;
    #pragma unroll
    for (int g = 0; g < 2; g++) {
        pk |= (i1[f * 2 + g] & 3) << (4 * g);
        pk |= (i1[F * 2 + f * 2 + g] & 3) << (4 * g + 2);
        dst[6 + g] = softcoef(args.cw1[layer] + (size_t)(f * 2 + g) * 16);
    }
    pk |= (i2[f] & 1) << 8;
    pk |= (i2[F + f] & 1) << 9;
    dst[8] = softcoef(args.cw2[layer] + (size_t)f * 16);
    dst[9] = make_float4(__int_as_float(pk), 0.f, 0.f, 0.f);
}

// ============================================================================
// Transpose + binarize: x[b][784] -> xT[p][BPAD] (pad lanes = 0).
// ============================================================================
__global__ __launch_bounds__(256)
void transpose_kernel(const float* __restrict__ x) {
    int tid = blockIdx.x * blockDim.x + threadIdx.x;   // 784 * 128
    int b = tid & (BPAD - 1);
    int p = tid >> 7;
    float v = 0.f;
    if (b < BATCH) v = (x[b * 784 + p] > 0.5f) ? 1.f : 0.f;
    g_xT[p * BPAD + b] = v;
}

// ============================================================================
// Conv(logic-tree) + 2x2 max-pool, feature-major, lane = batch.
// One thread = one pooled output for one batch; 4 pool positions serial,
// 8 fully-coalesced gathers each. Descriptor loads are warp-uniform.
// ============================================================================
template <int F, int POH, int POW, int WPAD, int OFSTR, int OW, int OHALO, int DOFF>
__global__ __launch_bounds__(256)
void conv_kernel(const float* __restrict__ in, float* __restrict__ out) {
    int w = blockIdx.x * 8 + (threadIdx.x >> 5);   // global warp id
    int lane = threadIdx.x & 31;
    int gidx = w >> 2;                              // gate = (f, pi, pj)
    int b = (w & 3) * 32 + lane;

    constexpr int NP = POH * POW;
    int f = gidx / NP, r = gidx - f * NP;
    int pi = r / POW, pj = r - pi * POW;

    const float4* D = g_desc + DOFF + f * 10;
    float4 s0 = __ldg(D + 0), s1 = __ldg(D + 1);
    int oa[4] = {__float_as_int(s0.x), __float_as_int(s0.y),
                 __float_as_int(s0.z), __float_as_int(s0.w)};
    int ob[4] = {__float_as_int(s1.x), __float_as_int(s1.y),
                 __float_as_int(s1.z), __float_as_int(s1.w)};
    float4 k0[4] = {__ldg(D + 2), __ldg(D + 3), __ldg(D + 4), __ldg(D + 5)};
    float4 k1[2] = {__ldg(D + 6), __ldg(D + 7)};
    float4 k2 = __ldg(D + 8);
    int pk = __float_as_int(__ldg(D + 9).x);
    int a10 = pk & 3, b10 = (pk >> 2) & 3, a11 = (pk >> 4) & 3, b11 = (pk >> 6) & 3;
    int a2 = (pk >> 8) & 1, b2 = (pk >> 9) & 1;

    float m = -1e30f;
    #pragma unroll
    for (int di = 0; di < 2; di++) {
        #pragma unroll
        for (int dj = 0; dj < 2; dj++) {
            const float* src = in + ((2 * pi + di) * WPAD + 2 * pj + dj) * BPAD + b;
            float av[4], bv[4];
            #pragma unroll
            for (int g = 0; g < 4; g++) { av[g] = __ldg(src + oa[g]); bv[g] = __ldg(src + ob[g]); }
            float h0[4];
            #pragma unroll
            for (int g = 0; g < 4; g++) h0[g] = gate(av[g], bv[g], k0[g]);
            float h1[2];
            h1[0] = gate(pick4(h0, a10), pick4(h0, b10), k1[0]);
            h1[1] = gate(pick4(h0, a11), pick4(h0, b11), k1[1]);
            float v = gate(a2 ? h1[1] : h1[0], b2 ? h1[1] : h1[0], k2);
            m = fmaxf(m, v);
        }
    }
    out[(f * OFSTR + (pi + OHALO) * OW + (pj + OHALO)) * BPAD + b] = m;
}

// ============================================================================
// FC layers, feature-major: warp = (output gate, batch quarter); lane = batch.
// ============================================================================
template <int DOUT, int COFF>
__global__ __launch_bounds__(256)
void fc_kernel(const float* __restrict__ inT, const int* __restrict__ idx,
               float* __restrict__ outT) {
    int w = blockIdx.x * 8 + (threadIdx.x >> 5);
    int lane = threadIdx.x & 31;
    int o  = w >> 2;
    int b  = (w & 3) * 32 + lane;
    int ia = __ldg(idx + o);
    int ib = __ldg(idx + DOUT + o);
    float4 k = g_coef[COFF + o];
    float v = gate(inT[ia * BPAD + b], inT[ib * BPAD + b], k);
    outT[o * BPAD + b] = v;
}

// fc3 + GroupSum(k=10, tau=30). grid = (10 groups, 4 batch-quarters), block 512.
__global__ __launch_bounds__(512)
void fc3_sum_kernel(const int* __restrict__ idx, float* __restrict__ out) {
    int grp = blockIdx.x, bq = blockIdx.y;
    int tid = threadIdx.x;
    int lane = tid & 31;
    int w = tid >> 5;                      // 0..15
    int b = bq * 32 + lane;

    float v = 0.f;
    #pragma unroll 4
    for (int kk = 0; kk < 32; kk++) {
        int o = grp * 512 + w * 32 + kk;
        int ia = __ldg(idx + o);
        int ib = __ldg(idx + 5120 + o);
        float4 c = g_coef[OFF_FC3 + o];
        v += gate(g_f2T[ia * BPAD + b], g_f2T[ib * BPAD + b], c);
    }
    __shared__ float sdata[16][33];
    sdata[w][lane] = v;
    __syncthreads();
    if (tid < 32) {
        float s = 0.f;
        #pragma unroll
        for (int ww = 0; ww < 16; ww++) s += sdata[ww][lane];
        if (b < BATCH) out[b * 10 + grp] = s / 30.0f;
    }
}

// ============================================================================
// Launch
// ============================================================================
extern "C" void kernel_launch(void* const* d_in, const int* in_sizes, int n_in,
                              void* d_out, int out_size) {
    const float* x    = (const float*)d_in[0];
    const int*   c1i0 = (const int*)d_in[1];   const float* c1w0 = (const float*)d_in[2];
    const int*   c1i1 = (const int*)d_in[3];   const float* c1w1 = (const float*)d_in[4];
    const int*   c1i2 = (const int*)d_in[5];   const float* c1w2 = (const float*)d_in[6];
    const int*   c2i0 = (const int*)d_in[7];   const float* c2w0 = (const float*)d_in[8];
    const int*   c2i1 = (const int*)d_in[9];   const float* c2w1 = (const float*)d_in[10];
    const int*   c2i2 = (const int*)d_in[11];  const float* c2w2 = (const float*)d_in[12];
    const int*   c3i0 = (const int*)d_in[13];  const float* c3w0 = (const float*)d_in[14];
    const int*   c3i1 = (const int*)d_in[15];  const float* c3w1 = (const float*)d_in[16];
    const int*   c3i2 = (const int*)d_in[17];  const float* c3w2 = (const float*)d_in[18];
    const int*   fc1i = (const int*)d_in[19];  const float* fc1w = (const float*)d_in[20];
    const int*   fc2i = (const int*)d_in[21];  const float* fc2w = (const float*)d_in[22];
    const int*   fc3i = (const int*)d_in[23];  const float* fc3w = (const float*)d_in[24];
    float* out = (float*)d_out;

    float *xT, *p1T, *p2T, *p3T, *f1T, *f2T;
    cudaGetSymbolAddress((void**)&xT,  g_xT);
    cudaGetSymbolAddress((void**)&p1T, g_p1T);
    cudaGetSymbolAddress((void**)&p2T, g_p2T);
    cudaGetSymbolAddress((void**)&p3T, g_p3T);
    cudaGetSymbolAddress((void**)&f1T, g_f1T);
    cudaGetSymbolAddress((void**)&f2T, g_f2T);

    // 1) prep: fc coefs + conv filter descriptors (offsets pre-scaled by BPAD)
    PrepArgs pa;
    pa.fc1w = fc1w; pa.fc2w = fc2w; pa.fc3w = fc3w;
    pa.ci0[0] = c1i0; pa.ci1[0] = c1i1; pa.ci2[0] = c1i2;
    pa.cw0[0] = c1w0; pa.cw1[0] = c1w1; pa.cw2[0] = c1w2;
    pa.ci0[1] = c2i0; pa.ci1[1] = c2i1; pa.ci2[1] = c2i2;
    pa.cw0[1] = c2w0; pa.cw1[1] = c2w1; pa.cw2[1] = c2w2;
    pa.ci0[2] = c3i0; pa.ci1[2] = c3i1; pa.ci2[2] = c3i2;
    pa.cw0[2] = c3w0; pa.cw1[2] = c3w1; pa.cw2[2] = c3w2;
    prep_kernel<<<(N_FCC + 208 + 255) / 256, 256>>>(pa);

    // 2) transpose + binarize: x[100][784] -> xT[784][128]
    transpose_kernel<<<784 * BPAD / 256, 256>>>(x);

    // 3) conv1 + pool: xT -> p1T [16*196][128] halo=1   (2304 gates * 4 bq = 9216 warps)
    conv_kernel<16, 12, 12, 28, 196, 14, 1, DESC_C1>
        <<<16 * 144 * 4 / 8, 256>>>(xT, p1T);
    // 4) conv2 + pool: p1T -> p2T [48*64][128] halo=1   (1728 gates -> 6912 warps)
    conv_kernel<48, 6, 6, 14, 64, 8, 1, DESC_C2>
        <<<48 * 36 * 4 / 8, 256>>>(p1T, p2T);
    // 5) conv3 + pool: p2T -> p3T [1296][128]           (1296 gates -> 5184 warps)
    conv_kernel<144, 3, 3, 8, 9, 3, 0, DESC_C3>
        <<<144 * 9 * 4 / 8, 256>>>(p2T, p3T);
    // 6) fc1: 1296 -> 20480
    fc_kernel<20480, OFF_FC1><<<20480 * 4 / 8, 256>>>(p3T, fc1i, f1T);
    // 7) fc2: 20480 -> 10240
    fc_kernel<10240, OFF_FC2><<<10240 * 4 / 8, 256>>>(f1T, fc2i, f2T);
    // 8) fc3 + group sum -> [100, 10]
    {
        dim3 grid(10, 4);
        fc3_sum_kernel<<<grid, 512>>>(fc3i, out);
    }
    (void)in_sizes; (void)n_in; (void)out_size;
}

// round 11
// speedup vs baseline: 1.3363x; 1.2362x over previous
#include <cuda_runtime.h>

#define DEVINLINE __device__ __forceinline__

constexpr int BATCH = 100;
constexpr int BPAD  = 128;   // padded batch stride; lanes cover batches

// --- fc coefficient offsets (gates, float4 units) ---
constexpr int OFF_FC1 = 0;        // 20480
constexpr int OFF_FC2 = 20480;    // 10240
constexpr int OFF_FC3 = 30720;    // 5120
constexpr int N_FCC   = 35840;

// conv descriptor slots (float4 units): 10 slots per filter
constexpr int DESC_C1 = 0;            // 16 filters
constexpr int DESC_C2 = 16 * 10;      // 48 filters
constexpr int DESC_C3 = 64 * 10;      // 144 filters
constexpr int N_DESC  = 208 * 10;

// --- scratch (device globals; zero-initialized; halo positions never written) ---
__device__ float4 g_coef[N_FCC];
__device__ float4 g_desc[N_DESC];
__device__ float  g_xT [784 * BPAD];            // binarized input, [pos][BPAD]
__device__ float  g_p1T[16 * 196 * BPAD];       // conv1 pooled, halo=1
__device__ float  g_p2T[48 * 64 * BPAD];        // conv2 pooled, halo=1
__device__ float  g_p3T[1296 * BPAD];           // conv3 pooled (ref flatten order)
__device__ float  g_f1T[20480 * BPAD];
__device__ float  g_f2T[10240 * BPAD];

// softmax(w[16]) -> fused gate coefficients (C, A, B, D):  op = C + A*a + B*b + D*ab
DEVINLINE float4 softcoef(const float* __restrict__ w) {
    const float4* w4 = (const float4*)w;
    float4 q0 = __ldg(w4 + 0), q1 = __ldg(w4 + 1), q2 = __ldg(w4 + 2), q3 = __ldg(w4 + 3);
    float v[16] = {q0.x, q0.y, q0.z, q0.w, q1.x, q1.y, q1.z, q1.w,
                   q2.x, q2.y, q2.z, q2.w, q3.x, q3.y, q3.z, q3.w};
    float mx = -1e30f;
    #pragma unroll
    for (int i = 0; i < 16; i++) mx = fmaxf(mx, v[i]);
    float sum = 0.f;
    #pragma unroll
    for (int i = 0; i < 16; i++) { v[i] = __expf(v[i] - mx); sum += v[i]; }
    float inv = 1.0f / sum;
    #pragma unroll
    for (int i = 0; i < 16; i++) v[i] *= inv;
    float C = v[8] + v[9] + v[10] + v[11] + v[12] + v[13] + v[14] + v[15];
    float A = v[2] + v[3] + v[6] + v[7] - v[8] - v[9] - v[12] - v[13];
    float B = v[4] + v[5] + v[6] + v[7] - v[8] - v[9] - v[10] - v[11];
    float D = v[1] - v[2] - v[4] - 2.f * v[6] - v[7]
            + v[8] + 2.f * v[9] + v[11] + v[13] - v[14];
    return make_float4(C, A, B, D);
}

DEVINLINE float gate(float a, float b, float4 k) {
    return fmaf(a, fmaf(k.w, b, k.y), fmaf(k.z, b, k.x));
}
DEVINLINE float2 gate2(float2 a, float2 b, float4 k) {
    float2 r;
    r.x = fmaf(a.x, fmaf(k.w, b.x, k.y), fmaf(k.z, b.x, k.x));
    r.y = fmaf(a.y, fmaf(k.w, b.y, k.y), fmaf(k.z, b.y, k.x));
    return r;
}
DEVINLINE float4 gate4(float4 a, float4 b, float4 k) {
    float4 r;
    r.x = fmaf(a.x, fmaf(k.w, b.x, k.y), fmaf(k.z, b.x, k.x));
    r.y = fmaf(a.y, fmaf(k.w, b.y, k.y), fmaf(k.z, b.y, k.x));
    r.z = fmaf(a.z, fmaf(k.w, b.z, k.y), fmaf(k.z, b.z, k.x));
    r.w = fmaf(a.w, fmaf(k.w, b.w, k.y), fmaf(k.z, b.w, k.x));
    return r;
}
DEVINLINE float2 pick4_2(const float2 h[4], int i) {
    float2 r = h[0];
    r = (i == 1) ? h[1] : r;
    r = (i == 2) ? h[2] : r;
    r = (i == 3) ? h[3] : r;
    return r;
}

// ============================================================================
// Prep kernel: fc coefficients + conv filter descriptors (offsets * BPAD).
// ============================================================================
struct PrepArgs {
    const float* fc1w; const float* fc2w; const float* fc3w;
    const int*   ci0[3]; const int* ci1[3]; const int* ci2[3];
    const float* cw0[3]; const float* cw1[3]; const float* cw2[3];
};

__constant__ int c_F[3]    = {16, 48, 144};
__constant__ int c_KS[3]   = {5, 3, 3};
__constant__ int c_CSTR[3] = {784, 196, 64};
__constant__ int c_WPAD[3] = {28, 14, 8};
__constant__ int c_DOFF[3] = {DESC_C1, DESC_C2, DESC_C3};

__global__ void prep_kernel(PrepArgs args) {
    int tid = blockIdx.x * blockDim.x + threadIdx.x;
    if (tid < N_FCC) {
        const float* w;
        int g;
        if (tid < OFF_FC2)      { w = args.fc1w; g = tid; }
        else if (tid < OFF_FC3) { w = args.fc2w; g = tid - OFF_FC2; }
        else                    { w = args.fc3w; g = tid - OFF_FC3; }
        g_coef[tid] = softcoef(w + (size_t)g * 16);
        return;
    }
    int j = tid - N_FCC;
    if (j >= 208) return;
    int layer, f;
    if (j < 16)      { layer = 0; f = j; }
    else if (j < 64) { layer = 1; f = j - 16; }
    else             { layer = 2; f = j - 64; }

    int F = c_F[layer], KS = c_KS[layer], CSTR = c_CSTR[layer], WP = c_WPAD[layer];
    const int* i0 = args.ci0[layer];
    const int* i1 = args.ci1[layer];
    const int* i2 = args.ci2[layer];
    float4* dst = g_desc + c_DOFF[layer] + f * 10;

    int offA[4], offB[4];
    #pragma unroll
    for (int g = 0; g < 4; g++) {
        int ta = i0[f * 4 + g], tb = i0[F * 4 + f * 4 + g];
        int ca = ta / (KS * KS), ra = ta - ca * KS * KS;
        int cb = tb / (KS * KS), rb = tb - cb * KS * KS;
        offA[g] = (ca * CSTR + (ra / KS) * WP + (ra % KS)) * BPAD;
        offB[g] = (cb * CSTR + (rb / KS) * WP + (rb % KS)) * BPAD;
        dst[2 + g] = softcoef(args.cw0[layer] + (size_t)(f * 4 + g) * 16);
    }
    dst[0] = make_float4(__int_as_float(offA[0]), __int_as_float(offA[1]),
                         __int_as_float(offA[2]), __int_as_float(offA[3]));
    dst[1] = make_float4(__int_as_float(offB[0]), __int_as_float(offB[1]),
                         __int_as_float(offB[2]), __int_as_float(offB[3]));
    int pk = 0;
    #pragma unroll
    for (int g = 0; g < 2; g++) {
        pk |= (i1[f * 2 + g] & 3) << (4 * g);
        pk |= (i1[F * 2 + f * 2 + g] & 3) << (4 * g + 2);
        dst[6 + g] = softcoef(args.cw1[layer] + (size_t)(f * 2 + g) * 16);
    }
    pk |= (i2[f] & 1) << 8;
    pk |= (i2[F + f] & 1) << 9;
    dst[8] = softcoef(args.cw2[layer] + (size_t)f * 16);
    dst[9] = make_float4(__int_as_float(pk), 0.f, 0.f, 0.f);
}

// ============================================================================
// Transpose + binarize: x[b][784] -> xT[p][BPAD] (pad lanes = 0).
// ============================================================================
__global__ __launch_bounds__(256)
void transpose_kernel(const float* __restrict__ x) {
    int tid = blockIdx.x * blockDim.x + threadIdx.x;   // 784 * 128
    int b = tid & (BPAD - 1);
    int p = tid >> 7;
    float v = 0.f;
    if (b < BATCH) v = (x[b * 784 + p] > 0.5f) ? 1.f : 0.f;
    g_xT[p * BPAD + b] = v;
}

// ============================================================================
// Conv(logic-tree) + 2x2 max-pool, feature-major.
// warp = (gate, batch-half); lane = 2 batches (float2).
// Loads hoisted per position-pair (MLP=16); pool max in registers.
// ============================================================================
template <int F, int POH, int POW, int WPAD, int OFSTR, int OW, int OHALO, int DOFF>
__global__ __launch_bounds__(128)
void conv_kernel(const float* __restrict__ in, float* __restrict__ out) {
    int w = blockIdx.x * 4 + (threadIdx.x >> 5);   // global warp id
    int lane = threadIdx.x & 31;
    int gidx = w >> 1;                             // gate = (f, pi, pj)
    int b0 = (w & 1) * 64 + 2 * lane;

    constexpr int NP = POH * POW;
    int f = gidx / NP, r = gidx - f * NP;
    int pi = r / POW, pj = r - pi * POW;

    const float4* D = g_desc + DOFF + f * 10;
    float4 s0 = __ldg(D + 0), s1 = __ldg(D + 1);
    int oa[4] = {__float_as_int(s0.x), __float_as_int(s0.y),
                 __float_as_int(s0.z), __float_as_int(s0.w)};
    int ob[4] = {__float_as_int(s1.x), __float_as_int(s1.y),
                 __float_as_int(s1.z), __float_as_int(s1.w)};
    float4 k0[4] = {__ldg(D + 2), __ldg(D + 3), __ldg(D + 4), __ldg(D + 5)};
    float4 k1[2] = {__ldg(D + 6), __ldg(D + 7)};
    float4 k2 = __ldg(D + 8);
    int pk = __float_as_int(__ldg(D + 9).x);
    int a10 = pk & 3, b10 = (pk >> 2) & 3, a11 = (pk >> 4) & 3, b11 = (pk >> 6) & 3;
    int a2 = (pk >> 8) & 1, b2 = (pk >> 9) & 1;

    float2 m = make_float2(-1e30f, -1e30f);
    #pragma unroll
    for (int di = 0; di < 2; di++) {
        // hoist both dj positions' 16 loads before any math
        float2 A[2][4], Bv[2][4];
        #pragma unroll
        for (int dj = 0; dj < 2; dj++) {
            const float* src = in + ((2 * pi + di) * WPAD + 2 * pj + dj) * BPAD + b0;
            #pragma unroll
            for (int g = 0; g < 4; g++) {
                A[dj][g]  = __ldg((const float2*)(src + oa[g]));
                Bv[dj][g] = __ldg((const float2*)(src + ob[g]));
            }
        }
        #pragma unroll
        for (int dj = 0; dj < 2; dj++) {
            float2 h0[4];
            #pragma unroll
            for (int g = 0; g < 4; g++) h0[g] = gate2(A[dj][g], Bv[dj][g], k0[g]);
            float2 h1[2];
            h1[0] = gate2(pick4_2(h0, a10), pick4_2(h0, b10), k1[0]);
            h1[1] = gate2(pick4_2(h0, a11), pick4_2(h0, b11), k1[1]);
            float2 v = gate2(a2 ? h1[1] : h1[0], b2 ? h1[1] : h1[0], k2);
            m.x = fmaxf(m.x, v.x);
            m.y = fmaxf(m.y, v.y);
        }
    }
    *(float2*)(out + (f * OFSTR + (pi + OHALO) * OW + (pj + OHALO)) * BPAD + b0) = m;
}

// ============================================================================
// FC layers: warp = output gate; lane = 4 batches (float4).
// ============================================================================
template <int DOUT, int COFF>
__global__ __launch_bounds__(256)
void fc_kernel(const float* __restrict__ inT, const int* __restrict__ idx,
               float* __restrict__ outT) {
    int o = blockIdx.x * 8 + (threadIdx.x >> 5);
    int b = (threadIdx.x & 31) * 4;
    int ia = __ldg(idx + o);
    int ib = __ldg(idx + DOUT + o);
    float4 k = g_coef[COFF + o];
    float4 a  = __ldg((const float4*)(inT + ia * BPAD + b));
    float4 bb = __ldg((const float4*)(inT + ib * BPAD + b));
    *(float4*)(outT + o * BPAD + b) = gate4(a, bb, k);
}

// fc3 + GroupSum(k=10, tau=30). grid = 10 groups, block 512 (16 warps).
__global__ __launch_bounds__(512)
void fc3_sum_kernel(const int* __restrict__ idx, float* __restrict__ out) {
    int grp = blockIdx.x;
    int tid = threadIdx.x;
    int lane = tid & 31;
    int w = tid >> 5;                      // 0..15
    int b = lane * 4;

    float4 acc = make_float4(0.f, 0.f, 0.f, 0.f);
    #pragma unroll 4
    for (int kk = 0; kk < 32; kk++) {
        int o = grp * 512 + w * 32 + kk;
        int ia = __ldg(idx + o);
        int ib = __ldg(idx + 5120 + o);
        float4 c = g_coef[OFF_FC3 + o];
        float4 a  = __ldg((const float4*)(g_f2T + ia * BPAD + b));
        float4 bb = __ldg((const float4*)(g_f2T + ib * BPAD + b));
        float4 v = gate4(a, bb, c);
        acc.x += v.x; acc.y += v.y; acc.z += v.z; acc.w += v.w;
    }
    __shared__ float4 sdata[16][32];
    sdata[w][lane] = acc;
    __syncthreads();
    if (w == 0) {
        float4 s = make_float4(0.f, 0.f, 0.f, 0.f);
        #pragma unroll
        for (int ww = 0; ww < 16; ww++) {
            float4 t = sdata[ww][lane];
            s.x += t.x; s.y += t.y; s.z += t.z; s.w += t.w;
        }
        const float inv = 1.0f / 30.0f;
        if (b     < BATCH) out[(b    ) * 10 + grp] = s.x * inv;
        if (b + 1 < BATCH) out[(b + 1) * 10 + grp] = s.y * inv;
        if (b + 2 < BATCH) out[(b + 2) * 10 + grp] = s.z * inv;
        if (b + 3 < BATCH) out[(b + 3) * 10 + grp] = s.w * inv;
    }
}

// ============================================================================
// Launch
// ============================================================================
extern "C" void kernel_launch(void* const* d_in, const int* in_sizes, int n_in,
                              void* d_out, int out_size) {
    const float* x    = (const float*)d_in[0];
    const int*   c1i0 = (const int*)d_in[1];   const float* c1w0 = (const float*)d_in[2];
    const int*   c1i1 = (const int*)d_in[3];   const float* c1w1 = (const float*)d_in[4];
    const int*   c1i2 = (const int*)d_in[5];   const float* c1w2 = (const float*)d_in[6];
    const int*   c2i0 = (const int*)d_in[7];   const float* c2w0 = (const float*)d_in[8];
    const int*   c2i1 = (const int*)d_in[9];   const float* c2w1 = (const float*)d_in[10];
    const int*   c2i2 = (const int*)d_in[11];  const float* c2w2 = (const float*)d_in[12];
    const int*   c3i0 = (const int*)d_in[13];  const float* c3w0 = (const float*)d_in[14];
    const int*   c3i1 = (const int*)d_in[15];  const float* c3w1 = (const float*)d_in[16];
    const int*   c3i2 = (const int*)d_in[17];  const float* c3w2 = (const float*)d_in[18];
    const int*   fc1i = (const int*)d_in[19];  const float* fc1w = (const float*)d_in[20];
    const int*   fc2i = (const int*)d_in[21];  const float* fc2w = (const float*)d_in[22];
    const int*   fc3i = (const int*)d_in[23];  const float* fc3w = (const float*)d_in[24];
    float* out = (float*)d_out;

    float *xT, *p1T, *p2T, *p3T, *f1T, *f2T;
    cudaGetSymbolAddress((void**)&xT,  g_xT);
    cudaGetSymbolAddress((void**)&p1T, g_p1T);
    cudaGetSymbolAddress((void**)&p2T, g_p2T);
    cudaGetSymbolAddress((void**)&p3T, g_p3T);
    cudaGetSymbolAddress((void**)&f1T, g_f1T);
    cudaGetSymbolAddress((void**)&f2T, g_f2T);

    // 1) prep
    PrepArgs pa;
    pa.fc1w = fc1w; pa.fc2w = fc2w; pa.fc3w = fc3w;
    pa.ci0[0] = c1i0; pa.ci1[0] = c1i1; pa.ci2[0] = c1i2;
    pa.cw0[0] = c1w0; pa.cw1[0] = c1w1; pa.cw2[0] = c1w2;
    pa.ci0[1] = c2i0; pa.ci1[1] = c2i1; pa.ci2[1] = c2i2;
    pa.cw0[1] = c2w0; pa.cw1[1] = c2w1; pa.cw2[1] = c2w2;
    pa.ci0[2] = c3i0; pa.ci1[2] = c3i1; pa.ci2[2] = c3i2;
    pa.cw0[2] = c3w0; pa.cw1[2] = c3w1; pa.cw2[2] = c3w2;
    prep_kernel<<<(N_FCC + 208 + 255) / 256, 256>>>(pa);

    // 2) transpose + binarize: x[100][784] -> xT[784][128]
    transpose_kernel<<<784 * BPAD / 256, 256>>>(x);

    // 3) conv1 + pool: xT -> p1T (2304 gates * 2 half-warps / 4 warps per block)
    conv_kernel<16, 12, 12, 28, 196, 14, 1, DESC_C1>
        <<<16 * 144 * 2 / 4, 128>>>(xT, p1T);
    // 4) conv2 + pool
    conv_kernel<48, 6, 6, 14, 64, 8, 1, DESC_C2>
        <<<48 * 36 * 2 / 4, 128>>>(p1T, p2T);
    // 5) conv3 + pool
    conv_kernel<144, 3, 3, 8, 9, 3, 0, DESC_C3>
        <<<144 * 9 * 2 / 4, 128>>>(p2T, p3T);
    // 6) fc1: 1296 -> 20480 (warp per output, float4 lanes)
    fc_kernel<20480, OFF_FC1><<<20480 / 8, 256>>>(p3T, fc1i, f1T);
    // 7) fc2: 20480 -> 10240
    fc_kernel<10240, OFF_FC2><<<10240 / 8, 256>>>(f1T, fc2i, f2T);
    // 8) fc3 + group sum -> [100, 10]
    fc3_sum_kernel<<<10, 512>>>(fc3i, out);
    (void)in_sizes; (void)n_in; (void)out_size;
}